// round 1
// baseline (speedup 1.0000x reference)
#include <cuda_runtime.h>
#include <cuda_bf16.h>
#include <cstdint>

// ---------------------------------------------------------------------------
// SentimentGAT: 3-layer GAT (H=4,F=64 / H=4,F=64 / H=1,F=64) + linear classifier
// N=30000 nodes, E=480000 edges (+N self loops), D_IN=5000, fp32 throughout.
// ---------------------------------------------------------------------------

#define GAT_N   30000
#define GAT_E   480000
#define GAT_E2  (GAT_E + GAT_N)
#define GAT_DIN 5000
#define GAT_HF  256      // 4 heads * 64
#define GAT_F   64

// ---- scratch (static device globals; no allocation in kernel_launch) ----
__device__ float g_hA[GAT_N * GAT_HF];     // 30.72 MB
__device__ float g_hB[GAT_N * GAT_HF];     // 30.72 MB
__device__ float g_h3[GAT_N * GAT_F];      // 7.68 MB
__device__ float g_acc3[GAT_N * GAT_F];    // 7.68 MB
__device__ float g_es[GAT_N * 4];
__device__ float g_ed[GAT_N * 4];
__device__ float g_ew[GAT_E2 * 4];         // 8.16 MB
__device__ float g_den[GAT_N * 4];

// ---------------------------------------------------------------------------
// vector red.global.add (sm_90+)
// ---------------------------------------------------------------------------
__device__ __forceinline__ void red_add_v4(float* addr, float4 v) {
    asm volatile("red.global.add.v4.f32 [%0], {%1,%2,%3,%4};"
                 :: "l"(addr), "f"(v.x), "f"(v.y), "f"(v.z), "f"(v.w)
                 : "memory");
}

// ---------------------------------------------------------------------------
// zero fill
// ---------------------------------------------------------------------------
__global__ void zerok(float4* p, int n4) {
    int i = blockIdx.x * blockDim.x + threadIdx.x;
    if (i < n4) p[i] = make_float4(0.f, 0.f, 0.f, 0.f);
}

// ---------------------------------------------------------------------------
// tiled fp32 SGEMM: C[M,N] = A[M,K] @ B[K,N]
// BM x BN block tile, BK k-tile, TM x TN per-thread microtile.
// Requires N % BN == 0 (true for all our calls); M, K guarded.
// ---------------------------------------------------------------------------
template <int BM, int BN, int BK, int TM, int TN>
__global__ __launch_bounds__((BM / TM) * (BN / TN))
void sgemm(const float* __restrict__ A, const float* __restrict__ B,
           float* __restrict__ C, int M, int N, int K) {
    constexpr int NTHREADS = (BM / TM) * (BN / TN);
    __shared__ float As[BK][BM];
    __shared__ float Bs[BK][BN];

    const int bm0 = blockIdx.y * BM;
    const int bn0 = blockIdx.x * BN;
    const int tid = threadIdx.x;
    const int tx = tid % (BN / TN);
    const int ty = tid / (BN / TN);

    float acc[TM][TN];
#pragma unroll
    for (int i = 0; i < TM; i++)
#pragma unroll
        for (int j = 0; j < TN; j++) acc[i][j] = 0.f;

    constexpr int AQ = BK / 4;          // float4 quads per A row
    constexpr int ATOT = BM * AQ;
    constexpr int BQ = BN / 4;
    constexpr int BTOT = BK * BQ;

    const int KT = (K + BK - 1) / BK;
    for (int kt = 0; kt < KT; kt++) {
        const int k0 = kt * BK;
        // load A tile (transposed into As[k][m])
#pragma unroll
        for (int i = tid; i < ATOT; i += NTHREADS) {
            int row = i / AQ, q = i % AQ;
            int gm = bm0 + row;
            int gk = k0 + q * 4;
            float4 v = make_float4(0.f, 0.f, 0.f, 0.f);
            if (gm < M) {
                if (gk + 4 <= K) {
                    v = *(const float4*)(A + (size_t)gm * K + gk);
                } else {
                    float t[4] = {0.f, 0.f, 0.f, 0.f};
                    for (int c = 0; c < 4; c++)
                        if (gk + c < K) t[c] = A[(size_t)gm * K + gk + c];
                    v = make_float4(t[0], t[1], t[2], t[3]);
                }
            }
            As[q * 4 + 0][row] = v.x;
            As[q * 4 + 1][row] = v.y;
            As[q * 4 + 2][row] = v.z;
            As[q * 4 + 3][row] = v.w;
        }
        // load B tile
#pragma unroll
        for (int i = tid; i < BTOT; i += NTHREADS) {
            int kr = i / BQ, q = i % BQ;
            int gk = k0 + kr;
            float4 v = make_float4(0.f, 0.f, 0.f, 0.f);
            if (gk < K)
                v = *(const float4*)(B + (size_t)gk * N + bn0 + q * 4);
            *(float4*)(&Bs[kr][q * 4]) = v;
        }
        __syncthreads();

#pragma unroll
        for (int kk = 0; kk < BK; kk++) {
            float a_r[TM], b_r[TN];
#pragma unroll
            for (int i = 0; i < TM; i += 4)
                *(float4*)(&a_r[i]) = *(const float4*)(&As[kk][ty * TM + i]);
#pragma unroll
            for (int j = 0; j < TN; j += 4)
                *(float4*)(&b_r[j]) = *(const float4*)(&Bs[kk][tx * TN + j]);
#pragma unroll
            for (int i = 0; i < TM; i++)
#pragma unroll
                for (int j = 0; j < TN; j++)
                    acc[i][j] = fmaf(a_r[i], b_r[j], acc[i][j]);
        }
        __syncthreads();
    }

#pragma unroll
    for (int i = 0; i < TM; i++) {
        int gm = bm0 + ty * TM + i;
        if (gm >= M) continue;
#pragma unroll
        for (int j = 0; j < TN; j += 4)
            *(float4*)(C + (size_t)gm * N + bn0 + tx * TN + j) =
                *(float4*)(&acc[i][j]);
    }
}

// ---------------------------------------------------------------------------
// per-(node,head) attention logits: es[n,h] = <h[n,h,:], a_src[h,:]>, same for ed
// one warp per (node,head)
// ---------------------------------------------------------------------------
template <int H>
__global__ void node_logits(const float* __restrict__ h,
                            const float* __restrict__ a_src,
                            const float* __restrict__ a_dst,
                            float* __restrict__ es, float* __restrict__ ed,
                            int n) {
    int w = (blockIdx.x * blockDim.x + threadIdx.x) >> 5;
    int lane = threadIdx.x & 31;
    if (w >= n * H) return;
    int node = w / H, head = w % H;
    const float* hp = h + (size_t)node * (H * 64) + head * 64;
    float h0 = hp[lane], h1 = hp[lane + 32];
    float s = h0 * a_src[head * 64 + lane] + h1 * a_src[head * 64 + lane + 32];
    float d = h0 * a_dst[head * 64 + lane] + h1 * a_dst[head * 64 + lane + 32];
#pragma unroll
    for (int o = 16; o; o >>= 1) {
        s += __shfl_xor_sync(0xffffffffu, s, o);
        d += __shfl_xor_sync(0xffffffffu, d, o);
    }
    if (lane == 0) { es[w] = s; ed[w] = d; }
}

// ---------------------------------------------------------------------------
// per-edge: e = leakyrelu(es[src]+ed[dst]); w = exp(e); den[dst] += w
// (softmax max-shift skipped: shift-invariant, logits are O(10), no overflow)
// ---------------------------------------------------------------------------
template <int H>
__global__ void edge_scores(const int* __restrict__ src,
                            const int* __restrict__ dst, int E_, int E2_,
                            const float* __restrict__ es,
                            const float* __restrict__ ed,
                            float* __restrict__ ew, float* __restrict__ den) {
    int t = blockIdx.x * blockDim.x + threadIdx.x;
    if (t >= E2_) return;
    int s, d;
    if (t < E_) { s = src[t]; d = dst[t]; }
    else        { s = t - E_; d = s; }
    if (H == 4) {
        float4 a = *(const float4*)(es + s * 4);
        float4 b = *(const float4*)(ed + d * 4);
        float4 w;
        float e;
        e = a.x + b.x; e = e > 0.f ? e : 0.2f * e; w.x = __expf(e);
        e = a.y + b.y; e = e > 0.f ? e : 0.2f * e; w.y = __expf(e);
        e = a.z + b.z; e = e > 0.f ? e : 0.2f * e; w.z = __expf(e);
        e = a.w + b.w; e = e > 0.f ? e : 0.2f * e; w.w = __expf(e);
        *(float4*)(ew + (size_t)t * 4) = w;
        red_add_v4(den + d * 4, w);
    } else {
        float e = es[s] + ed[d];
        e = e > 0.f ? e : 0.2f * e;
        float w = __expf(e);
        ew[t] = w;
        atomicAdd(den + d, w);
    }
}

// ---------------------------------------------------------------------------
// scatter-aggregate: acc[dst,h,:] += (ew/den[dst,h]) * h[src,h,:]
// one warp per edge; float4 gather + red.v4 scatter
// ---------------------------------------------------------------------------
template <int H>
__global__ void aggregate(const int* __restrict__ src,
                          const int* __restrict__ dst, int E_, int E2_,
                          const float* __restrict__ h,
                          const float* __restrict__ ew,
                          const float* __restrict__ den,
                          float* __restrict__ acc) {
    constexpr int HF = H * 64;
    int w = (blockIdx.x * blockDim.x + threadIdx.x) >> 5;
    int lane = threadIdx.x & 31;
    if (w >= E2_) return;
    int s, d;
    if (w < E_) { s = src[w]; d = dst[w]; }
    else        { s = w - E_; d = s; }
    const float* hp = h + (size_t)s * HF;
    float* ap = acc + (size_t)d * HF;
#pragma unroll
    for (int c = lane * 4; c < HF; c += 128) {
        int head = c >> 6;
        float alpha = __fdividef(ew[(size_t)w * H + head], den[d * H + head]);
        float4 v = *(const float4*)(hp + c);
        v.x *= alpha; v.y *= alpha; v.z *= alpha; v.w *= alpha;
        red_add_v4(ap + c, v);
    }
}

// ---------------------------------------------------------------------------
// elementwise: p = elu(p + b)  (in place)
// ---------------------------------------------------------------------------
__global__ void elu_bias(float* __restrict__ p, const float* __restrict__ b,
                         int total, int hf_mask) {
    int i = blockIdx.x * blockDim.x + threadIdx.x;
    if (i >= total) return;
    float v = p[i] + b[i & hf_mask];
    p[i] = v > 0.f ? v : expm1f(v);
}

// ---------------------------------------------------------------------------
// final: v = elu(acc3 + b3); out = v @ Wc + bc  (one warp per node)
// ---------------------------------------------------------------------------
__global__ void final_cls(const float* __restrict__ acc,
                          const float* __restrict__ b3,
                          const float* __restrict__ Wc,
                          const float* __restrict__ bc,
                          float* __restrict__ out, int n) {
    int w = (blockIdx.x * blockDim.x + threadIdx.x) >> 5;
    int lane = threadIdx.x & 31;
    if (w >= n) return;
    float v0 = acc[(size_t)w * 64 + lane] + b3[lane];
    v0 = v0 > 0.f ? v0 : expm1f(v0);
    float v1 = acc[(size_t)w * 64 + lane + 32] + b3[lane + 32];
    v1 = v1 > 0.f ? v1 : expm1f(v1);
#pragma unroll
    for (int j = 0; j < 3; j++) {
        float p = v0 * Wc[lane * 3 + j] + v1 * Wc[(lane + 32) * 3 + j];
#pragma unroll
        for (int o = 16; o; o >>= 1) p += __shfl_xor_sync(0xffffffffu, p, o);
        if (lane == 0) out[w * 3 + j] = p + bc[j];
    }
}

// ---------------------------------------------------------------------------
static inline int cdiv(int a, int b) { return (a + b - 1) / b; }

extern "C" void kernel_launch(void* const* d_in, const int* in_sizes, int n_in,
                              void* d_out, int out_size) {
    const float* x    = (const float*)d_in[0];
    const float* W1   = (const float*)d_in[1];
    const float* a1s  = (const float*)d_in[2];
    const float* a1d  = (const float*)d_in[3];
    const float* b1   = (const float*)d_in[4];
    const float* W2   = (const float*)d_in[5];
    const float* a2s  = (const float*)d_in[6];
    const float* a2d  = (const float*)d_in[7];
    const float* b2   = (const float*)d_in[8];
    const float* W3   = (const float*)d_in[9];
    const float* a3s  = (const float*)d_in[10];
    const float* a3d  = (const float*)d_in[11];
    const float* b3   = (const float*)d_in[12];
    const float* Wc   = (const float*)d_in[13];
    const float* bc   = (const float*)d_in[14];
    const int*   ei   = (const int*)d_in[15];
    float* out = (float*)d_out;

    const int N = GAT_N, E = GAT_E, E2 = GAT_E2;
    const int* src = ei;
    const int* dst = ei + E;

    float *hA, *hB, *h3, *acc3, *es, *ed, *ew, *den;
    cudaGetSymbolAddress((void**)&hA,   g_hA);
    cudaGetSymbolAddress((void**)&hB,   g_hB);
    cudaGetSymbolAddress((void**)&h3,   g_h3);
    cudaGetSymbolAddress((void**)&acc3, g_acc3);
    cudaGetSymbolAddress((void**)&es,   g_es);
    cudaGetSymbolAddress((void**)&ed,   g_ed);
    cudaGetSymbolAddress((void**)&ew,   g_ew);
    cudaGetSymbolAddress((void**)&den,  g_den);

    const int TB = 256;

    // ---------------- layer 1 (H=4) ----------------
    sgemm<128, 128, 16, 8, 8><<<dim3(2, cdiv(N, 128)), 256>>>(x, W1, hA, N, 256, GAT_DIN);
    node_logits<4><<<cdiv(N * 4 * 32, TB), TB>>>(hA, a1s, a1d, es, ed, N);
    zerok<<<cdiv(N, TB), TB>>>((float4*)den, N);                 // N*4/4
    zerok<<<cdiv(N * 64, TB), TB>>>((float4*)hB, N * 64);        // N*256/4
    edge_scores<4><<<cdiv(E2, TB), TB>>>(src, dst, E, E2, es, ed, ew, den);
    aggregate<4><<<cdiv(E2 * 32, TB), TB>>>(src, dst, E, E2, hA, ew, den, hB);
    elu_bias<<<cdiv(N * 256, TB), TB>>>(hB, b1, N * 256, 255);

    // ---------------- layer 2 (H=4) ----------------
    sgemm<128, 128, 16, 8, 8><<<dim3(2, cdiv(N, 128)), 256>>>(hB, W2, hA, N, 256, 256);
    node_logits<4><<<cdiv(N * 4 * 32, TB), TB>>>(hA, a2s, a2d, es, ed, N);
    zerok<<<cdiv(N, TB), TB>>>((float4*)den, N);
    zerok<<<cdiv(N * 64, TB), TB>>>((float4*)hB, N * 64);
    edge_scores<4><<<cdiv(E2, TB), TB>>>(src, dst, E, E2, es, ed, ew, den);
    aggregate<4><<<cdiv(E2 * 32, TB), TB>>>(src, dst, E, E2, hA, ew, den, hB);
    elu_bias<<<cdiv(N * 256, TB), TB>>>(hB, b2, N * 256, 255);

    // ---------------- layer 3 (H=1) ----------------
    sgemm<128, 64, 16, 8, 4><<<dim3(1, cdiv(N, 128)), 256>>>(hB, W3, h3, N, 64, 256);
    node_logits<1><<<cdiv(N * 32, TB), TB>>>(h3, a3s, a3d, es, ed, N);
    zerok<<<cdiv(N / 4, TB), TB>>>((float4*)den, N / 4);         // N*1/4
    zerok<<<cdiv(N * 16, TB), TB>>>((float4*)acc3, N * 16);      // N*64/4
    edge_scores<1><<<cdiv(E2, TB), TB>>>(src, dst, E, E2, es, ed, ew, den);
    aggregate<1><<<cdiv(E2 * 32, TB), TB>>>(src, dst, E, E2, h3, ew, den, acc3);
    final_cls<<<cdiv(N * 32, TB), TB>>>(acc3, b3, Wc, bc, out, N);
}

// round 3
// speedup vs baseline: 2.9188x; 2.9188x over previous
#include <cuda_runtime.h>
#include <cuda_bf16.h>
#include <cstdint>

// ---------------------------------------------------------------------------
// SentimentGAT on GB300 (sm_103 baseline PTX): bf16x3 mma.sync GEMMs +
// fp32 attention/scatter stack.
// N=30000 nodes, E=480000 edges (+N self loops), D_IN=5000.
// ---------------------------------------------------------------------------

#define GAT_N   30000
#define GAT_Mp  30080               // 235 * 128
#define GAT_E   480000
#define GAT_E2  (GAT_E + GAT_N)
#define GAT_DIN 5000
#define GAT_K1P 5056                // 79 * 64
#define GAT_HF  256
#define GAT_F   64

// ---- fp32 scratch ----
__device__ float g_hA[GAT_N * GAT_HF];
__device__ float g_hB[GAT_N * GAT_HF];
__device__ float g_h3[GAT_N * GAT_F];
__device__ float g_acc3[GAT_N * GAT_F];
__device__ float g_es[GAT_N * 4];
__device__ float g_ed[GAT_N * 4];
__device__ float g_ew[GAT_E2 * 4];
__device__ float g_den[GAT_N * 4];

// ---- bf16 hi/lo scratch ----
__device__ __align__(128) __nv_bfloat16 g_Ah[(size_t)GAT_Mp * GAT_K1P];
__device__ __align__(128) __nv_bfloat16 g_Al[(size_t)GAT_Mp * GAT_K1P];
__device__ __align__(128) __nv_bfloat16 g_Bh[256 * GAT_K1P];
__device__ __align__(128) __nv_bfloat16 g_Bl[256 * GAT_K1P];

// ===========================================================================
// low-level helpers (all baseline sm_80-class PTX)
// ===========================================================================
#define SWZ(o) ((o) ^ (((o) >> 3) & 0x70))

__device__ __forceinline__ uint32_t smem_u32(const void* p) {
    uint32_t a;
    asm("{ .reg .u64 t; cvta.to.shared.u64 t, %1; cvt.u32.u64 %0, t; }"
        : "=r"(a) : "l"(p));
    return a;
}
__device__ __forceinline__ void cp16(uint32_t d, const void* s) {
    asm volatile("cp.async.cg.shared.global [%0], [%1], 16;" :: "r"(d), "l"(s));
}
__device__ __forceinline__ void cp_commit() {
    asm volatile("cp.async.commit_group;" ::: "memory");
}
template <int Ng>
__device__ __forceinline__ void cp_wait() {
    asm volatile("cp.async.wait_group %0;" :: "n"(Ng) : "memory");
}
__device__ __forceinline__ void ldsm4(uint32_t (&r)[4], uint32_t addr) {
    asm volatile("ldmatrix.sync.aligned.m8n8.x4.shared.b16 {%0,%1,%2,%3}, [%4];"
                 : "=r"(r[0]), "=r"(r[1]), "=r"(r[2]), "=r"(r[3]) : "r"(addr));
}
__device__ __forceinline__ void mma16816(float (&d)[4], const uint32_t (&a)[4],
                                         uint32_t b0, uint32_t b1) {
    asm volatile("mma.sync.aligned.m16n8k16.row.col.f32.bf16.bf16.f32 "
                 "{%0,%1,%2,%3}, {%4,%5,%6,%7}, {%8,%9}, {%0,%1,%2,%3};"
                 : "+f"(d[0]), "+f"(d[1]), "+f"(d[2]), "+f"(d[3])
                 : "r"(a[0]), "r"(a[1]), "r"(a[2]), "r"(a[3]), "r"(b0), "r"(b1));
}

// ===========================================================================
// bf16x3 GEMM: C[M,N] = Ah@Bh^T + Ah@Bl^T + Al@Bh^T   (fp32 accumulate)
// A*: [Mp,Kp] bf16 row-major; B*: [N,Kp] bf16 row-major (W transposed).
// CTA tile 128 x BN, BK=32, 8 warps (warp tile 32 x BN/2), 2-stage cp.async.
// ===========================================================================
template <int BN>
__global__ __launch_bounds__(256)
void gemm_mma(const __nv_bfloat16* __restrict__ Ah, const __nv_bfloat16* __restrict__ Al,
              const __nv_bfloat16* __restrict__ Bh, const __nv_bfloat16* __restrict__ Bl,
              float* __restrict__ C, int M, int N, int Kp) {
    constexpr int WNCOL = BN / 2;           // columns per warp
    constexpr int NFRAG = WNCOL / 8;        // 8 or 4
    constexpr int NPAIR = NFRAG / 2;        // 4 or 2
    constexpr int ABH = 8192;               // one A half: 128 rows x 64B
    constexpr int BBH = BN * 64;            // one B half
    constexpr int STAGE = 2 * ABH + 2 * BBH;

    extern __shared__ char smem[];
    const uint32_t sb = smem_u32(smem);

    const int tid = threadIdx.x;
    const int wid = tid >> 5, lane = tid & 31;
    const int wm = wid & 3, wn = wid >> 2;
    const int bm0 = blockIdx.x * 128;
    const int bn0 = blockIdx.y * BN;

    float acc[2][NFRAG][4];
#pragma unroll
    for (int i = 0; i < 2; i++)
#pragma unroll
        for (int j = 0; j < NFRAG; j++)
#pragma unroll
            for (int k = 0; k < 4; k++) acc[i][j][k] = 0.f;

    const int NC = Kp >> 5;   // K tiles of 32

    auto load_stage = [&](int c, int stg) {
        const uint32_t base = sb + stg * STAGE;
        const size_t koff = (size_t)c * 32;
        // A: 2 halves x 128 rows x 4 chunks = 1024 cp16
#pragma unroll
        for (int t = 0; t < 4; t++) {
            int i = tid + t * 256;
            int half = i >> 9;
            int rem = i & 511;
            int row = rem >> 2, ch = rem & 3;
            const __nv_bfloat16* src =
                (half ? Al : Ah) + (size_t)(bm0 + row) * Kp + koff + ch * 8;
            cp16(base + half * ABH + SWZ(row * 64 + ch * 16), src);
        }
        // B: 2 halves x BN rows x 4 chunks
#pragma unroll
        for (int t = 0; t < BN / 32; t++) {
            int i = tid + t * 256;
            int half = i / (BN * 4);
            int rem = i % (BN * 4);
            int row = rem >> 2, ch = rem & 3;
            const __nv_bfloat16* src =
                (half ? Bl : Bh) + (size_t)(bn0 + row) * Kp + koff + ch * 8;
            cp16(base + 2 * ABH + half * BBH + SWZ(row * 64 + ch * 16), src);
        }
    };

    // lane-level ldmatrix offsets (logical, pre-swizzle)
    const int a_row = wm * 32 + (lane & 15);
    const int a_chb = lane >> 4;                          // 0/1
    const int b_row = wn * WNCOL + ((lane >> 4) & 1) * 8 + (lane & 7);
    const int b_chb = (lane >> 3) & 1;

    load_stage(0, 0);
    cp_commit();

    for (int c = 0; c < NC; c++) {
        if (c + 1 < NC) {
            load_stage(c + 1, (c + 1) & 1);
            cp_commit();
            cp_wait<1>();
        } else {
            cp_wait<0>();
        }
        __syncthreads();

        const uint32_t base = sb + (c & 1) * STAGE;
        const uint32_t aH = base, aL = base + ABH;
        const uint32_t bH = base + 2 * ABH, bL = bH + BBH;

#pragma unroll
        for (int ks = 0; ks < 2; ks++) {
            uint32_t ah[2][4], al[2][4];
#pragma unroll
            for (int mf = 0; mf < 2; mf++) {
                uint32_t off = SWZ((a_row + mf * 16) * 64 + (ks * 2 + a_chb) * 16);
                ldsm4(ah[mf], aH + off);
                ldsm4(al[mf], aL + off);
            }
            uint32_t bh[NPAIR][4], bl[NPAIR][4];
#pragma unroll
            for (int p = 0; p < NPAIR; p++) {
                uint32_t off = SWZ((b_row + p * 16) * 64 + (ks * 2 + b_chb) * 16);
                ldsm4(bh[p], bH + off);
                ldsm4(bl[p], bL + off);
            }
#pragma unroll
            for (int mf = 0; mf < 2; mf++)
#pragma unroll
                for (int p = 0; p < NPAIR; p++) {
                    mma16816(acc[mf][2 * p],     ah[mf], bh[p][0], bh[p][1]);
                    mma16816(acc[mf][2 * p],     ah[mf], bl[p][0], bl[p][1]);
                    mma16816(acc[mf][2 * p],     al[mf], bh[p][0], bh[p][1]);
                    mma16816(acc[mf][2 * p + 1], ah[mf], bh[p][2], bh[p][3]);
                    mma16816(acc[mf][2 * p + 1], ah[mf], bl[p][2], bl[p][3]);
                    mma16816(acc[mf][2 * p + 1], al[mf], bh[p][2], bh[p][3]);
                }
        }
        __syncthreads();
    }

    // epilogue
#pragma unroll
    for (int mf = 0; mf < 2; mf++) {
        int r0 = bm0 + wm * 32 + mf * 16 + (lane >> 2);
#pragma unroll
        for (int nf = 0; nf < NFRAG; nf++) {
            int col = bn0 + wn * WNCOL + nf * 8 + (lane & 3) * 2;
            if (r0 < M)
                *(float2*)(C + (size_t)r0 * N + col) =
                    make_float2(acc[mf][nf][0], acc[mf][nf][1]);
            if (r0 + 8 < M)
                *(float2*)(C + (size_t)(r0 + 8) * N + col) =
                    make_float2(acc[mf][nf][2], acc[mf][nf][3]);
        }
    }
}

// ===========================================================================
// conversions
// ===========================================================================
__global__ void conv_split(const float* __restrict__ X,
                           __nv_bfloat16* __restrict__ Hh,
                           __nv_bfloat16* __restrict__ Hl,
                           int M, int K, int Mp, int Kp) {
    int qn = Kp >> 2;
    long long idx = (long long)blockIdx.x * blockDim.x + threadIdx.x;
    if (idx >= (long long)Mp * qn) return;
    int row = (int)(idx / qn), q = (int)(idx - (long long)row * qn);
    float4 v = make_float4(0.f, 0.f, 0.f, 0.f);
    if (row < M && q * 4 < K) v = *(const float4*)(X + (size_t)row * K + q * 4);
    float vv[4] = {v.x, v.y, v.z, v.w};
    __nv_bfloat16 h[4], l[4];
#pragma unroll
    for (int j = 0; j < 4; j++) {
        h[j] = __float2bfloat16_rn(vv[j]);
        l[j] = __float2bfloat16_rn(vv[j] - __bfloat162float(h[j]));
    }
    size_t o = (size_t)row * Kp + q * 4;
    *(__nv_bfloat162*)(Hh + o)     = __nv_bfloat162(h[0], h[1]);
    *(__nv_bfloat162*)(Hh + o + 2) = __nv_bfloat162(h[2], h[3]);
    *(__nv_bfloat162*)(Hl + o)     = __nv_bfloat162(l[0], l[1]);
    *(__nv_bfloat162*)(Hl + o + 2) = __nv_bfloat162(l[2], l[3]);
}

__global__ void conv_wT(const float* __restrict__ W,
                        __nv_bfloat16* __restrict__ Bh,
                        __nv_bfloat16* __restrict__ Bl,
                        int K, int N, int Kp) {
    int idx = blockIdx.x * blockDim.x + threadIdx.x;
    if (idx >= N * Kp) return;
    int n = idx / Kp, k = idx - n * Kp;
    float v = (k < K) ? W[(size_t)k * N + n] : 0.f;
    __nv_bfloat16 h = __float2bfloat16_rn(v);
    __nv_bfloat16 l = __float2bfloat16_rn(v - __bfloat162float(h));
    Bh[(size_t)n * Kp + k] = h;
    Bl[(size_t)n * Kp + k] = l;
}

// ===========================================================================
// attention / elementwise stack (unchanged from R1 pass)
// ===========================================================================
__device__ __forceinline__ void red_add_v4(float* addr, float4 v) {
    asm volatile("red.global.add.v4.f32 [%0], {%1,%2,%3,%4};"
                 :: "l"(addr), "f"(v.x), "f"(v.y), "f"(v.z), "f"(v.w) : "memory");
}

__global__ void zerok(float4* p, int n4) {
    int i = blockIdx.x * blockDim.x + threadIdx.x;
    if (i < n4) p[i] = make_float4(0.f, 0.f, 0.f, 0.f);
}

template <int H>
__global__ void node_logits(const float* __restrict__ h,
                            const float* __restrict__ a_src,
                            const float* __restrict__ a_dst,
                            float* __restrict__ es, float* __restrict__ ed, int n) {
    int w = (blockIdx.x * blockDim.x + threadIdx.x) >> 5;
    int lane = threadIdx.x & 31;
    if (w >= n * H) return;
    int node = w / H, head = w % H;
    const float* hp = h + (size_t)node * (H * 64) + head * 64;
    float h0 = hp[lane], h1 = hp[lane + 32];
    float s = h0 * a_src[head * 64 + lane] + h1 * a_src[head * 64 + lane + 32];
    float d = h0 * a_dst[head * 64 + lane] + h1 * a_dst[head * 64 + lane + 32];
#pragma unroll
    for (int o = 16; o; o >>= 1) {
        s += __shfl_xor_sync(0xffffffffu, s, o);
        d += __shfl_xor_sync(0xffffffffu, d, o);
    }
    if (lane == 0) { es[w] = s; ed[w] = d; }
}

template <int H>
__global__ void edge_scores(const int* __restrict__ src, const int* __restrict__ dst,
                            int E_, int E2_, const float* __restrict__ es,
                            const float* __restrict__ ed,
                            float* __restrict__ ew, float* __restrict__ den) {
    int t = blockIdx.x * blockDim.x + threadIdx.x;
    if (t >= E2_) return;
    int s, d;
    if (t < E_) { s = src[t]; d = dst[t]; }
    else        { s = t - E_; d = s; }
    if (H == 4) {
        float4 a = *(const float4*)(es + s * 4);
        float4 b = *(const float4*)(ed + d * 4);
        float4 w; float e;
        e = a.x + b.x; e = e > 0.f ? e : 0.2f * e; w.x = __expf(e);
        e = a.y + b.y; e = e > 0.f ? e : 0.2f * e; w.y = __expf(e);
        e = a.z + b.z; e = e > 0.f ? e : 0.2f * e; w.z = __expf(e);
        e = a.w + b.w; e = e > 0.f ? e : 0.2f * e; w.w = __expf(e);
        *(float4*)(ew + (size_t)t * 4) = w;
        red_add_v4(den + d * 4, w);
    } else {
        float e = es[s] + ed[d];
        e = e > 0.f ? e : 0.2f * e;
        float w = __expf(e);
        ew[t] = w;
        atomicAdd(den + d, w);
    }
}

template <int H>
__global__ void aggregate(const int* __restrict__ src, const int* __restrict__ dst,
                          int E_, int E2_, const float* __restrict__ h,
                          const float* __restrict__ ew, const float* __restrict__ den,
                          float* __restrict__ acc) {
    constexpr int HF = H * 64;
    int w = (blockIdx.x * blockDim.x + threadIdx.x) >> 5;
    int lane = threadIdx.x & 31;
    if (w >= E2_) return;
    int s, d;
    if (w < E_) { s = src[w]; d = dst[w]; }
    else        { s = w - E_; d = s; }
    const float* hp = h + (size_t)s * HF;
    float* ap = acc + (size_t)d * HF;
#pragma unroll
    for (int c = lane * 4; c < HF; c += 128) {
        int head = c >> 6;
        float alpha = __fdividef(ew[(size_t)w * H + head], den[d * H + head]);
        float4 v = *(const float4*)(hp + c);
        v.x *= alpha; v.y *= alpha; v.z *= alpha; v.w *= alpha;
        red_add_v4(ap + c, v);
    }
}

__global__ void elu_bias(float* __restrict__ p, const float* __restrict__ b,
                         int total, int hf_mask) {
    int i = blockIdx.x * blockDim.x + threadIdx.x;
    if (i >= total) return;
    float v = p[i] + b[i & hf_mask];
    p[i] = v > 0.f ? v : expm1f(v);
}

__global__ void final_cls(const float* __restrict__ acc, const float* __restrict__ b3,
                          const float* __restrict__ Wc, const float* __restrict__ bc,
                          float* __restrict__ out, int n) {
    int w = (blockIdx.x * blockDim.x + threadIdx.x) >> 5;
    int lane = threadIdx.x & 31;
    if (w >= n) return;
    float v0 = acc[(size_t)w * 64 + lane] + b3[lane];
    v0 = v0 > 0.f ? v0 : expm1f(v0);
    float v1 = acc[(size_t)w * 64 + lane + 32] + b3[lane + 32];
    v1 = v1 > 0.f ? v1 : expm1f(v1);
#pragma unroll
    for (int j = 0; j < 3; j++) {
        float p = v0 * Wc[lane * 3 + j] + v1 * Wc[(lane + 32) * 3 + j];
#pragma unroll
        for (int o = 16; o; o >>= 1) p += __shfl_xor_sync(0xffffffffu, p, o);
        if (lane == 0) out[w * 3 + j] = p + bc[j];
    }
}

// ===========================================================================
static inline int cdiv(int a, int b) { return (a + b - 1) / b; }

extern "C" void kernel_launch(void* const* d_in, const int* in_sizes, int n_in,
                              void* d_out, int out_size) {
    const float* x    = (const float*)d_in[0];
    const float* W1   = (const float*)d_in[1];
    const float* a1s  = (const float*)d_in[2];
    const float* a1d  = (const float*)d_in[3];
    const float* b1   = (const float*)d_in[4];
    const float* W2   = (const float*)d_in[5];
    const float* a2s  = (const float*)d_in[6];
    const float* a2d  = (const float*)d_in[7];
    const float* b2   = (const float*)d_in[8];
    const float* W3   = (const float*)d_in[9];
    const float* a3s  = (const float*)d_in[10];
    const float* a3d  = (const float*)d_in[11];
    const float* b3   = (const float*)d_in[12];
    const float* Wc   = (const float*)d_in[13];
    const float* bc   = (const float*)d_in[14];
    const int*   ei   = (const int*)d_in[15];
    float* out = (float*)d_out;

    const int N = GAT_N, E = GAT_E, E2 = GAT_E2, Mp = GAT_Mp;
    const int* src = ei;
    const int* dst = ei + E;

    float *hA, *hB, *h3, *acc3, *es, *ed, *ew, *den;
    __nv_bfloat16 *Ahp, *Alp, *Bhp, *Blp;
    cudaGetSymbolAddress((void**)&hA,   g_hA);
    cudaGetSymbolAddress((void**)&hB,   g_hB);
    cudaGetSymbolAddress((void**)&h3,   g_h3);
    cudaGetSymbolAddress((void**)&acc3, g_acc3);
    cudaGetSymbolAddress((void**)&es,   g_es);
    cudaGetSymbolAddress((void**)&ed,   g_ed);
    cudaGetSymbolAddress((void**)&ew,   g_ew);
    cudaGetSymbolAddress((void**)&den,  g_den);
    cudaGetSymbolAddress((void**)&Ahp,  g_Ah);
    cudaGetSymbolAddress((void**)&Alp,  g_Al);
    cudaGetSymbolAddress((void**)&Bhp,  g_Bh);
    cudaGetSymbolAddress((void**)&Blp,  g_Bl);

    const int SM128 = 2 * (2 * 8192 + 2 * 128 * 64);   // 65536
    const int SM64  = 2 * (2 * 8192 + 2 * 64 * 64);    // 49152
    cudaFuncSetAttribute(gemm_mma<128>, cudaFuncAttributeMaxDynamicSharedMemorySize, SM128);
    cudaFuncSetAttribute(gemm_mma<64>,  cudaFuncAttributeMaxDynamicSharedMemorySize, SM64);

    const int TB = 256;
    const int MT = Mp / 128;   // 235

    // ---------------- layer 1 (H=4, K=5000->5056) ----------------
    {
        long long tot = (long long)Mp * (GAT_K1P / 4);
        conv_split<<<(int)((tot + TB - 1) / TB), TB>>>(x, Ahp, Alp, N, GAT_DIN, Mp, GAT_K1P);
        conv_wT<<<cdiv(256 * GAT_K1P, TB), TB>>>(W1, Bhp, Blp, GAT_DIN, 256, GAT_K1P);
        gemm_mma<128><<<dim3(MT, 2), 256, SM128>>>(Ahp, Alp, Bhp, Blp, hA, N, 256, GAT_K1P);
    }
    node_logits<4><<<cdiv(N * 4 * 32, TB), TB>>>(hA, a1s, a1d, es, ed, N);
    zerok<<<cdiv(N, TB), TB>>>((float4*)den, N);
    zerok<<<cdiv(N * 64, TB), TB>>>((float4*)hB, N * 64);
    edge_scores<4><<<cdiv(E2, TB), TB>>>(src, dst, E, E2, es, ed, ew, den);
    aggregate<4><<<cdiv(E2 * 32, TB), TB>>>(src, dst, E, E2, hA, ew, den, hB);
    elu_bias<<<cdiv(N * 256, TB), TB>>>(hB, b1, N * 256, 255);

    // ---------------- layer 2 (H=4, K=256) ----------------
    {
        long long tot = (long long)Mp * (256 / 4);
        conv_split<<<(int)((tot + TB - 1) / TB), TB>>>(hB, Ahp, Alp, N, 256, Mp, 256);
        conv_wT<<<cdiv(256 * 256, TB), TB>>>(W2, Bhp, Blp, 256, 256, 256);
        gemm_mma<128><<<dim3(MT, 2), 256, SM128>>>(Ahp, Alp, Bhp, Blp, hA, N, 256, 256);
    }
    node_logits<4><<<cdiv(N * 4 * 32, TB), TB>>>(hA, a2s, a2d, es, ed, N);
    zerok<<<cdiv(N, TB), TB>>>((float4*)den, N);
    zerok<<<cdiv(N * 64, TB), TB>>>((float4*)hB, N * 64);
    edge_scores<4><<<cdiv(E2, TB), TB>>>(src, dst, E, E2, es, ed, ew, den);
    aggregate<4><<<cdiv(E2 * 32, TB), TB>>>(src, dst, E, E2, hA, ew, den, hB);
    elu_bias<<<cdiv(N * 256, TB), TB>>>(hB, b2, N * 256, 255);

    // ---------------- layer 3 (H=1, K=256, N=64) ----------------
    {
        long long tot = (long long)Mp * (256 / 4);
        conv_split<<<(int)((tot + TB - 1) / TB), TB>>>(hB, Ahp, Alp, N, 256, Mp, 256);
        conv_wT<<<cdiv(64 * 256, TB), TB>>>(W3, Bhp, Blp, 256, 64, 256);
        gemm_mma<64><<<dim3(MT, 1), 256, SM64>>>(Ahp, Alp, Bhp, Blp, h3, N, 64, 256);
    }
    node_logits<1><<<cdiv(N * 32, TB), TB>>>(h3, a3s, a3d, es, ed, N);
    zerok<<<cdiv(N / 4, TB), TB>>>((float4*)den, N / 4);
    zerok<<<cdiv(N * 16, TB), TB>>>((float4*)acc3, N * 16);
    edge_scores<1><<<cdiv(E2, TB), TB>>>(src, dst, E, E2, es, ed, ew, den);
    aggregate<1><<<cdiv(E2 * 32, TB), TB>>>(src, dst, E, E2, h3, ew, den, acc3);
    final_cls<<<cdiv(N * 32, TB), TB>>>(acc3, b3, Wc, bc, out, N);
}

// round 4
// speedup vs baseline: 3.1415x; 1.0763x over previous
#include <cuda_runtime.h>
#include <cuda_bf16.h>
#include <cstdint>

// ---------------------------------------------------------------------------
// SentimentGAT on GB300 (sm_103 baseline PTX): bf16x3 mma.sync GEMMs with
// fused fp32->bf16 hi/lo conversion, fp32 attention/scatter stack.
// ---------------------------------------------------------------------------

#define GAT_N   30000
#define GAT_Mp  30080               // 235 * 128
#define GAT_E   480000
#define GAT_E2  (GAT_E + GAT_N)
#define GAT_DIN 5000
#define GAT_K1P 5056                // 79 * 64 (padded K stride for W1^T)
#define GAT_HF  256
#define GAT_F   64

// ---- fp32 scratch ----
__device__ float g_hA[GAT_N * GAT_HF];
__device__ float g_hB[GAT_N * GAT_HF];
__device__ float g_h3[GAT_N * GAT_F];
__device__ float g_acc3[GAT_N * GAT_F];
__device__ float g_es[GAT_N * 4];
__device__ float g_ed[GAT_N * 4];
__device__ float g_ew[GAT_E2 * 4];
__device__ float g_den[GAT_N * 4];

// ---- bf16 hi/lo scratch (A only needed for layers 2/3 now) ----
__device__ __align__(128) __nv_bfloat16 g_Ah[(size_t)GAT_Mp * GAT_HF];
__device__ __align__(128) __nv_bfloat16 g_Al[(size_t)GAT_Mp * GAT_HF];
__device__ __align__(128) __nv_bfloat16 g_Bh[256 * GAT_K1P];
__device__ __align__(128) __nv_bfloat16 g_Bl[256 * GAT_K1P];

// ===========================================================================
// low-level helpers
// ===========================================================================
#define SWZ(o) ((o) ^ (((o) >> 3) & 0x70))

__device__ __forceinline__ uint32_t smem_u32(const void* p) {
    uint32_t a;
    asm("{ .reg .u64 t; cvta.to.shared.u64 t, %1; cvt.u32.u64 %0, t; }"
        : "=r"(a) : "l"(p));
    return a;
}
__device__ __forceinline__ void cp16(uint32_t d, const void* s) {
    asm volatile("cp.async.cg.shared.global [%0], [%1], 16;" :: "r"(d), "l"(s));
}
// zero-fill variant: src-size 0 -> smem gets zeros, src not dereferenced
__device__ __forceinline__ void cp16z(uint32_t d, const void* s, bool pred) {
    int sz = pred ? 16 : 0;
    asm volatile("cp.async.cg.shared.global [%0], [%1], 16, %2;"
                 :: "r"(d), "l"(s), "r"(sz));
}
__device__ __forceinline__ void cp_commit() {
    asm volatile("cp.async.commit_group;" ::: "memory");
}
template <int Ng>
__device__ __forceinline__ void cp_wait() {
    asm volatile("cp.async.wait_group %0;" :: "n"(Ng) : "memory");
}
__device__ __forceinline__ void ldsm4(uint32_t (&r)[4], uint32_t addr) {
    asm volatile("ldmatrix.sync.aligned.m8n8.x4.shared.b16 {%0,%1,%2,%3}, [%4];"
                 : "=r"(r[0]), "=r"(r[1]), "=r"(r[2]), "=r"(r[3]) : "r"(addr));
}
__device__ __forceinline__ void mma16816(float (&d)[4], const uint32_t (&a)[4],
                                         uint32_t b0, uint32_t b1) {
    asm volatile("mma.sync.aligned.m16n8k16.row.col.f32.bf16.bf16.f32 "
                 "{%0,%1,%2,%3}, {%4,%5,%6,%7}, {%8,%9}, {%0,%1,%2,%3};"
                 : "+f"(d[0]), "+f"(d[1]), "+f"(d[2]), "+f"(d[3])
                 : "r"(a[0]), "r"(a[1]), "r"(a[2]), "r"(a[3]), "r"(b0), "r"(b1));
}
__device__ __forceinline__ uint32_t bfpack(float a, float b) {
    return (uint32_t)__bfloat16_as_ushort(__float2bfloat16_rn(a)) |
           ((uint32_t)__bfloat16_as_ushort(__float2bfloat16_rn(b)) << 16);
}

// ===========================================================================
// FUSED layer-1 GEMM: C[M,256] = split3(X) @ split3(W1)^T
// X: [M,K] fp32 row-major (read directly, zero-filled tails)
// Bh/Bl: [256,KpB] bf16 row-major. CTA tile 128x128, BK=32, 8 warps.
// Per K-tile: cp.async fp32 A -> smem, convert to hi/lo bf16 smem, mma.
// ===========================================================================
__global__ __launch_bounds__(256)
void gemm_fused(const float* __restrict__ X,
                const __nv_bfloat16* __restrict__ Bh, const __nv_bfloat16* __restrict__ Bl,
                float* __restrict__ C, int M, int K, int KpB) {
    // stage layout (per stage, 49152 B):
    //   AF fp32 : 0     .. 16384
    //   AH bf16 : 16384 .. 24576
    //   AL bf16 : 24576 .. 32768
    //   BH bf16 : 32768 .. 40960
    //   BL bf16 : 40960 .. 49152
    constexpr int STAGE = 49152;
    extern __shared__ char smem[];
    const uint32_t sb = smem_u32(smem);

    const int tid = threadIdx.x;
    const int wid = tid >> 5, lane = tid & 31;
    const int wm = wid & 3, wn = wid >> 2;
    const int bm0 = blockIdx.x * 128;
    const int bn0 = blockIdx.y * 128;

    float acc[2][8][4];
#pragma unroll
    for (int i = 0; i < 2; i++)
#pragma unroll
        for (int j = 0; j < 8; j++)
#pragma unroll
            for (int k = 0; k < 4; k++) acc[i][j][k] = 0.f;

    const int NC = (K + 31) >> 5;

    auto load_stage = [&](int c, int stg) {
        const uint32_t base = sb + stg * STAGE;
        const int k0 = c * 32;
        // A fp32: 128 rows x 8 cp16 (4 floats each) = 1024
#pragma unroll
        for (int t = 0; t < 4; t++) {
            int i = tid + t * 256;
            int row = i >> 3, q = i & 7;
            int gm = bm0 + row, gk = k0 + q * 4;
            bool p = (gm < M) && (gk < K);
            cp16z(base + row * 128 + q * 16, X + (p ? ((size_t)gm * K + gk) : 0), p);
        }
        // B bf16 hi/lo: 2 x 128 rows x 4 cp16
#pragma unroll
        for (int t = 0; t < 4; t++) {
            int i = tid + t * 256;
            int half = i >> 9;
            int rem = i & 511;
            int row = rem >> 2, ch = rem & 3;
            const __nv_bfloat16* src =
                (half ? Bl : Bh) + (size_t)(bn0 + row) * KpB + k0 + ch * 8;
            cp16(base + 32768 + half * 8192 + SWZ(row * 64 + ch * 16), src);
        }
    };

    const int a_row = wm * 32 + (lane & 15);
    const int a_chb = lane >> 4;
    const int b_row = wn * 64 + ((lane >> 4) & 1) * 8 + (lane & 7);
    const int b_chb = (lane >> 3) & 1;

    load_stage(0, 0);
    cp_commit();

    for (int c = 0; c < NC; c++) {
        const int stg = c & 1;
        const uint32_t base = sb + stg * STAGE;
        cp_wait<0>();
        __syncthreads();
        // convert AF (fp32) -> AH/AL (bf16 hi/lo), 512 tasks of 8 floats
#pragma unroll
        for (int t = 0; t < 2; t++) {
            int i = tid + t * 256;
            int row = i >> 2, ch = i & 3;
            const float4* fp = (const float4*)(smem + stg * STAGE + row * 128 + ch * 32);
            float4 v0 = fp[0], v1 = fp[1];
            float f[8] = {v0.x, v0.y, v0.z, v0.w, v1.x, v1.y, v1.z, v1.w};
            uint32_t hi[4], lo[4];
#pragma unroll
            for (int k = 0; k < 4; k++) {
                float h0 = __bfloat162float(__float2bfloat16_rn(f[2 * k]));
                float h1 = __bfloat162float(__float2bfloat16_rn(f[2 * k + 1]));
                hi[k] = bfpack(f[2 * k], f[2 * k + 1]);
                lo[k] = bfpack(f[2 * k] - h0, f[2 * k + 1] - h1);
            }
            uint32_t off = SWZ(row * 64 + ch * 16);
            *(uint4*)(smem + stg * STAGE + 16384 + off) = make_uint4(hi[0], hi[1], hi[2], hi[3]);
            *(uint4*)(smem + stg * STAGE + 24576 + off) = make_uint4(lo[0], lo[1], lo[2], lo[3]);
        }
        __syncthreads();
        if (c + 1 < NC) {
            load_stage(c + 1, stg ^ 1);
            cp_commit();
        }

        const uint32_t aH = base + 16384, aL = base + 24576;
        const uint32_t bH = base + 32768, bL = base + 40960;
#pragma unroll
        for (int ks = 0; ks < 2; ks++) {
            uint32_t ah[2][4], al[2][4];
#pragma unroll
            for (int mf = 0; mf < 2; mf++) {
                uint32_t off = SWZ((a_row + mf * 16) * 64 + (ks * 2 + a_chb) * 16);
                ldsm4(ah[mf], aH + off);
                ldsm4(al[mf], aL + off);
            }
            uint32_t bh[4][4], bl[4][4];
#pragma unroll
            for (int p = 0; p < 4; p++) {
                uint32_t off = SWZ((b_row + p * 16) * 64 + (ks * 2 + b_chb) * 16);
                ldsm4(bh[p], bH + off);
                ldsm4(bl[p], bL + off);
            }
#pragma unroll
            for (int mf = 0; mf < 2; mf++)
#pragma unroll
                for (int p = 0; p < 4; p++) {
                    mma16816(acc[mf][2 * p],     ah[mf], bh[p][0], bh[p][1]);
                    mma16816(acc[mf][2 * p],     ah[mf], bl[p][0], bl[p][1]);
                    mma16816(acc[mf][2 * p],     al[mf], bh[p][0], bh[p][1]);
                    mma16816(acc[mf][2 * p + 1], ah[mf], bh[p][2], bh[p][3]);
                    mma16816(acc[mf][2 * p + 1], ah[mf], bl[p][2], bl[p][3]);
                    mma16816(acc[mf][2 * p + 1], al[mf], bh[p][2], bh[p][3]);
                }
        }
    }

#pragma unroll
    for (int mf = 0; mf < 2; mf++) {
        int r0 = bm0 + wm * 32 + mf * 16 + (lane >> 2);
#pragma unroll
        for (int nf = 0; nf < 8; nf++) {
            int col = bn0 + wn * 64 + nf * 8 + (lane & 3) * 2;
            if (r0 < M)
                *(float2*)(C + (size_t)r0 * 256 + col) =
                    make_float2(acc[mf][nf][0], acc[mf][nf][1]);
            if (r0 + 8 < M)
                *(float2*)(C + (size_t)(r0 + 8) * 256 + col) =
                    make_float2(acc[mf][nf][2], acc[mf][nf][3]);
        }
    }
}

// ===========================================================================
// pre-split GEMM for layers 2/3 (A already hi/lo bf16): unchanged from R3
// ===========================================================================
template <int BN>
__global__ __launch_bounds__(256)
void gemm_mma(const __nv_bfloat16* __restrict__ Ah, const __nv_bfloat16* __restrict__ Al,
              const __nv_bfloat16* __restrict__ Bh, const __nv_bfloat16* __restrict__ Bl,
              float* __restrict__ C, int M, int N, int Kp) {
    constexpr int WNCOL = BN / 2;
    constexpr int NFRAG = WNCOL / 8;
    constexpr int NPAIR = NFRAG / 2;
    constexpr int ABH = 8192;
    constexpr int BBH = BN * 64;
    constexpr int STAGE = 2 * ABH + 2 * BBH;

    extern __shared__ char smem[];
    const uint32_t sb = smem_u32(smem);

    const int tid = threadIdx.x;
    const int wid = tid >> 5, lane = tid & 31;
    const int wm = wid & 3, wn = wid >> 2;
    const int bm0 = blockIdx.x * 128;
    const int bn0 = blockIdx.y * BN;

    float acc[2][NFRAG][4];
#pragma unroll
    for (int i = 0; i < 2; i++)
#pragma unroll
        for (int j = 0; j < NFRAG; j++)
#pragma unroll
            for (int k = 0; k < 4; k++) acc[i][j][k] = 0.f;

    const int NC = Kp >> 5;

    auto load_stage = [&](int c, int stg) {
        const uint32_t base = sb + stg * STAGE;
        const size_t koff = (size_t)c * 32;
#pragma unroll
        for (int t = 0; t < 4; t++) {
            int i = tid + t * 256;
            int half = i >> 9;
            int rem = i & 511;
            int row = rem >> 2, ch = rem & 3;
            const __nv_bfloat16* src =
                (half ? Al : Ah) + (size_t)(bm0 + row) * Kp + koff + ch * 8;
            cp16(base + half * ABH + SWZ(row * 64 + ch * 16), src);
        }
#pragma unroll
        for (int t = 0; t < BN / 32; t++) {
            int i = tid + t * 256;
            int half = i / (BN * 4);
            int rem = i % (BN * 4);
            int row = rem >> 2, ch = rem & 3;
            const __nv_bfloat16* src =
                (half ? Bl : Bh) + (size_t)(bn0 + row) * Kp + koff + ch * 8;
            cp16(base + 2 * ABH + half * BBH + SWZ(row * 64 + ch * 16), src);
        }
    };

    const int a_row = wm * 32 + (lane & 15);
    const int a_chb = lane >> 4;
    const int b_row = wn * WNCOL + ((lane >> 4) & 1) * 8 + (lane & 7);
    const int b_chb = (lane >> 3) & 1;

    load_stage(0, 0);
    cp_commit();

    for (int c = 0; c < NC; c++) {
        if (c + 1 < NC) {
            load_stage(c + 1, (c + 1) & 1);
            cp_commit();
            cp_wait<1>();
        } else {
            cp_wait<0>();
        }
        __syncthreads();

        const uint32_t base = sb + (c & 1) * STAGE;
        const uint32_t aH = base, aL = base + ABH;
        const uint32_t bH = base + 2 * ABH, bL = bH + BBH;

#pragma unroll
        for (int ks = 0; ks < 2; ks++) {
            uint32_t ah[2][4], al[2][4];
#pragma unroll
            for (int mf = 0; mf < 2; mf++) {
                uint32_t off = SWZ((a_row + mf * 16) * 64 + (ks * 2 + a_chb) * 16);
                ldsm4(ah[mf], aH + off);
                ldsm4(al[mf], aL + off);
            }
            uint32_t bh[NPAIR][4], bl[NPAIR][4];
#pragma unroll
            for (int p = 0; p < NPAIR; p++) {
                uint32_t off = SWZ((b_row + p * 16) * 64 + (ks * 2 + b_chb) * 16);
                ldsm4(bh[p], bH + off);
                ldsm4(bl[p], bL + off);
            }
#pragma unroll
            for (int mf = 0; mf < 2; mf++)
#pragma unroll
                for (int p = 0; p < NPAIR; p++) {
                    mma16816(acc[mf][2 * p],     ah[mf], bh[p][0], bh[p][1]);
                    mma16816(acc[mf][2 * p],     ah[mf], bl[p][0], bl[p][1]);
                    mma16816(acc[mf][2 * p],     al[mf], bh[p][0], bh[p][1]);
                    mma16816(acc[mf][2 * p + 1], ah[mf], bh[p][2], bh[p][3]);
                    mma16816(acc[mf][2 * p + 1], ah[mf], bl[p][2], bl[p][3]);
                    mma16816(acc[mf][2 * p + 1], al[mf], bh[p][2], bh[p][3]);
                }
        }
        __syncthreads();
    }

#pragma unroll
    for (int mf = 0; mf < 2; mf++) {
        int r0 = bm0 + wm * 32 + mf * 16 + (lane >> 2);
#pragma unroll
        for (int nf = 0; nf < NFRAG; nf++) {
            int col = bn0 + wn * WNCOL + nf * 8 + (lane & 3) * 2;
            if (r0 < M)
                *(float2*)(C + (size_t)r0 * N + col) =
                    make_float2(acc[mf][nf][0], acc[mf][nf][1]);
            if (r0 + 8 < M)
                *(float2*)(C + (size_t)(r0 + 8) * N + col) =
                    make_float2(acc[mf][nf][2], acc[mf][nf][3]);
        }
    }
}

// ===========================================================================
// conversions
// ===========================================================================
// fused bias + ELU + hi/lo split (K fixed 256): H = elu(X + b) -> Hh, Hl
__global__ void conv_split_be(const float* __restrict__ X, const float* __restrict__ b,
                              __nv_bfloat16* __restrict__ Hh,
                              __nv_bfloat16* __restrict__ Hl, int M, int Mp) {
    int idx = blockIdx.x * blockDim.x + threadIdx.x;
    if (idx >= Mp * 64) return;
    int row = idx >> 6, q = idx & 63;
    float4 v = make_float4(0.f, 0.f, 0.f, 0.f);
    if (row < M) {
        v = *(const float4*)(X + (size_t)row * 256 + q * 4);
        float4 bb = *(const float4*)(b + q * 4);
        v.x += bb.x; v.y += bb.y; v.z += bb.z; v.w += bb.w;
        v.x = v.x > 0.f ? v.x : expm1f(v.x);
        v.y = v.y > 0.f ? v.y : expm1f(v.y);
        v.z = v.z > 0.f ? v.z : expm1f(v.z);
        v.w = v.w > 0.f ? v.w : expm1f(v.w);
    }
    float f[4] = {v.x, v.y, v.z, v.w};
    __nv_bfloat16 h[4], l[4];
#pragma unroll
    for (int j = 0; j < 4; j++) {
        h[j] = __float2bfloat16_rn(f[j]);
        l[j] = __float2bfloat16_rn(f[j] - __bfloat162float(h[j]));
    }
    size_t o = (size_t)row * 256 + q * 4;
    *(__nv_bfloat162*)(Hh + o)     = __nv_bfloat162(h[0], h[1]);
    *(__nv_bfloat162*)(Hh + o + 2) = __nv_bfloat162(h[2], h[3]);
    *(__nv_bfloat162*)(Hl + o)     = __nv_bfloat162(l[0], l[1]);
    *(__nv_bfloat162*)(Hl + o + 2) = __nv_bfloat162(l[2], l[3]);
}

// W [K,N] fp32 -> hi/lo bf16 [N,Kp]
__global__ void conv_wT(const float* __restrict__ W,
                        __nv_bfloat16* __restrict__ Bh,
                        __nv_bfloat16* __restrict__ Bl,
                        int K, int N, int Kp) {
    int idx = blockIdx.x * blockDim.x + threadIdx.x;
    if (idx >= N * Kp) return;
    int n = idx / Kp, k = idx - n * Kp;
    float v = (k < K) ? W[(size_t)k * N + n] : 0.f;
    __nv_bfloat16 h = __float2bfloat16_rn(v);
    __nv_bfloat16 l = __float2bfloat16_rn(v - __bfloat162float(h));
    Bh[(size_t)n * Kp + k] = h;
    Bl[(size_t)n * Kp + k] = l;
}

// ===========================================================================
// attention / elementwise stack
// ===========================================================================
__device__ __forceinline__ void red_add_v4(float* addr, float4 v) {
    asm volatile("red.global.add.v4.f32 [%0], {%1,%2,%3,%4};"
                 :: "l"(addr), "f"(v.x), "f"(v.y), "f"(v.z), "f"(v.w) : "memory");
}

__global__ void zerok(float4* p, int n4) {
    int i = blockIdx.x * blockDim.x + threadIdx.x;
    if (i < n4) p[i] = make_float4(0.f, 0.f, 0.f, 0.f);
}

// also zeroes den[w] (same index space) to save a pass
template <int H>
__global__ void node_logits(const float* __restrict__ h,
                            const float* __restrict__ a_src,
                            const float* __restrict__ a_dst,
                            float* __restrict__ es, float* __restrict__ ed,
                            float* __restrict__ den, int n) {
    int w = (blockIdx.x * blockDim.x + threadIdx.x) >> 5;
    int lane = threadIdx.x & 31;
    if (w >= n * H) return;
    int node = w / H, head = w % H;
    const float* hp = h + (size_t)node * (H * 64) + head * 64;
    float h0 = hp[lane], h1 = hp[lane + 32];
    float s = h0 * a_src[head * 64 + lane] + h1 * a_src[head * 64 + lane + 32];
    float d = h0 * a_dst[head * 64 + lane] + h1 * a_dst[head * 64 + lane + 32];
#pragma unroll
    for (int o = 16; o; o >>= 1) {
        s += __shfl_xor_sync(0xffffffffu, s, o);
        d += __shfl_xor_sync(0xffffffffu, d, o);
    }
    if (lane == 0) { es[w] = s; ed[w] = d; den[w] = 0.f; }
}

template <int H>
__global__ void edge_scores(const int* __restrict__ src, const int* __restrict__ dst,
                            int E_, int E2_, const float* __restrict__ es,
                            const float* __restrict__ ed,
                            float* __restrict__ ew, float* __restrict__ den) {
    int t = blockIdx.x * blockDim.x + threadIdx.x;
    if (t >= E2_) return;
    int s, d;
    if (t < E_) { s = src[t]; d = dst[t]; }
    else        { s = t - E_; d = s; }
    if (H == 4) {
        float4 a = *(const float4*)(es + s * 4);
        float4 b = *(const float4*)(ed + d * 4);
        float4 w; float e;
        e = a.x + b.x; e = e > 0.f ? e : 0.2f * e; w.x = __expf(e);
        e = a.y + b.y; e = e > 0.f ? e : 0.2f * e; w.y = __expf(e);
        e = a.z + b.z; e = e > 0.f ? e : 0.2f * e; w.z = __expf(e);
        e = a.w + b.w; e = e > 0.f ? e : 0.2f * e; w.w = __expf(e);
        *(float4*)(ew + (size_t)t * 4) = w;
        red_add_v4(den + d * 4, w);
    } else {
        float e = es[s] + ed[d];
        e = e > 0.f ? e : 0.2f * e;
        float w = __expf(e);
        ew[t] = w;
        atomicAdd(den + d, w);
    }
}

template <int H>
__global__ void aggregate(const int* __restrict__ src, const int* __restrict__ dst,
                          int E_, int E2_, const float* __restrict__ h,
                          const float* __restrict__ ew, const float* __restrict__ den,
                          float* __restrict__ acc) {
    constexpr int HF = H * 64;
    int w = (blockIdx.x * blockDim.x + threadIdx.x) >> 5;
    int lane = threadIdx.x & 31;
    if (w >= E2_) return;
    int s, d;
    if (w < E_) { s = src[w]; d = dst[w]; }
    else        { s = w - E_; d = s; }
    const float* hp = h + (size_t)s * HF;
    float* ap = acc + (size_t)d * HF;
#pragma unroll
    for (int c = lane * 4; c < HF; c += 128) {
        int head = c >> 6;
        float alpha = __fdividef(ew[(size_t)w * H + head], den[d * H + head]);
        float4 v = *(const float4*)(hp + c);
        v.x *= alpha; v.y *= alpha; v.z *= alpha; v.w *= alpha;
        red_add_v4(ap + c, v);
    }
}

__global__ void final_cls(const float* __restrict__ acc, const float* __restrict__ b3,
                          const float* __restrict__ Wc, const float* __restrict__ bc,
                          float* __restrict__ out, int n) {
    int w = (blockIdx.x * blockDim.x + threadIdx.x) >> 5;
    int lane = threadIdx.x & 31;
    if (w >= n) return;
    float v0 = acc[(size_t)w * 64 + lane] + b3[lane];
    v0 = v0 > 0.f ? v0 : expm1f(v0);
    float v1 = acc[(size_t)w * 64 + lane + 32] + b3[lane + 32];
    v1 = v1 > 0.f ? v1 : expm1f(v1);
#pragma unroll
    for (int j = 0; j < 3; j++) {
        float p = v0 * Wc[lane * 3 + j] + v1 * Wc[(lane + 32) * 3 + j];
#pragma unroll
        for (int o = 16; o; o >>= 1) p += __shfl_xor_sync(0xffffffffu, p, o);
        if (lane == 0) out[w * 3 + j] = p + bc[j];
    }
}

// ===========================================================================
static inline int cdiv(int a, int b) { return (a + b - 1) / b; }

extern "C" void kernel_launch(void* const* d_in, const int* in_sizes, int n_in,
                              void* d_out, int out_size) {
    const float* x    = (const float*)d_in[0];
    const float* W1   = (const float*)d_in[1];
    const float* a1s  = (const float*)d_in[2];
    const float* a1d  = (const float*)d_in[3];
    const float* b1   = (const float*)d_in[4];
    const float* W2   = (const float*)d_in[5];
    const float* a2s  = (const float*)d_in[6];
    const float* a2d  = (const float*)d_in[7];
    const float* b2   = (const float*)d_in[8];
    const float* W3   = (const float*)d_in[9];
    const float* a3s  = (const float*)d_in[10];
    const float* a3d  = (const float*)d_in[11];
    const float* b3   = (const float*)d_in[12];
    const float* Wc   = (const float*)d_in[13];
    const float* bc   = (const float*)d_in[14];
    const int*   ei   = (const int*)d_in[15];
    float* out = (float*)d_out;

    const int N = GAT_N, E = GAT_E, E2 = GAT_E2, Mp = GAT_Mp;
    const int* src = ei;
    const int* dst = ei + E;

    float *hA, *hB, *h3, *acc3, *es, *ed, *ew, *den;
    __nv_bfloat16 *Ahp, *Alp, *Bhp, *Blp;
    cudaGetSymbolAddress((void**)&hA,   g_hA);
    cudaGetSymbolAddress((void**)&hB,   g_hB);
    cudaGetSymbolAddress((void**)&h3,   g_h3);
    cudaGetSymbolAddress((void**)&acc3, g_acc3);
    cudaGetSymbolAddress((void**)&es,   g_es);
    cudaGetSymbolAddress((void**)&ed,   g_ed);
    cudaGetSymbolAddress((void**)&ew,   g_ew);
    cudaGetSymbolAddress((void**)&den,  g_den);
    cudaGetSymbolAddress((void**)&Ahp,  g_Ah);
    cudaGetSymbolAddress((void**)&Alp,  g_Al);
    cudaGetSymbolAddress((void**)&Bhp,  g_Bh);
    cudaGetSymbolAddress((void**)&Blp,  g_Bl);

    const int SMF   = 2 * 49152;                       // fused gemm
    const int SM128 = 2 * (2 * 8192 + 2 * 128 * 64);   // 65536
    const int SM64  = 2 * (2 * 8192 + 2 * 64 * 64);    // 49152
    cudaFuncSetAttribute(gemm_fused,    cudaFuncAttributeMaxDynamicSharedMemorySize, SMF);
    cudaFuncSetAttribute(gemm_mma<128>, cudaFuncAttributeMaxDynamicSharedMemorySize, SM128);
    cudaFuncSetAttribute(gemm_mma<64>,  cudaFuncAttributeMaxDynamicSharedMemorySize, SM64);

    const int TB = 256;
    const int MT = Mp / 128;   // 235

    // ---------------- layer 1 (H=4, K=5000) ----------------
    conv_wT<<<cdiv(256 * GAT_K1P, TB), TB>>>(W1, Bhp, Blp, GAT_DIN, 256, GAT_K1P);
    gemm_fused<<<dim3(MT, 2), 256, SMF>>>(x, Bhp, Blp, hA, N, GAT_DIN, GAT_K1P);
    node_logits<4><<<cdiv(N * 4 * 32, TB), TB>>>(hA, a1s, a1d, es, ed, den, N);
    zerok<<<cdiv(N * 64, TB), TB>>>((float4*)hB, N * 64);
    edge_scores<4><<<cdiv(E2, TB), TB>>>(src, dst, E, E2, es, ed, ew, den);
    aggregate<4><<<cdiv(E2 * 32, TB), TB>>>(src, dst, E, E2, hA, ew, den, hB);

    // ---------------- layer 2 (H=4, K=256) ----------------
    conv_split_be<<<cdiv(Mp * 64, TB), TB>>>(hB, b1, Ahp, Alp, N, Mp);
    conv_wT<<<cdiv(256 * 256, TB), TB>>>(W2, Bhp, Blp, 256, 256, 256);
    gemm_mma<128><<<dim3(MT, 2), 256, SM128>>>(Ahp, Alp, Bhp, Blp, hA, N, 256, 256);
    node_logits<4><<<cdiv(N * 4 * 32, TB), TB>>>(hA, a2s, a2d, es, ed, den, N);
    zerok<<<cdiv(N * 64, TB), TB>>>((float4*)hB, N * 64);
    edge_scores<4><<<cdiv(E2, TB), TB>>>(src, dst, E, E2, es, ed, ew, den);
    aggregate<4><<<cdiv(E2 * 32, TB), TB>>>(src, dst, E, E2, hA, ew, den, hB);

    // ---------------- layer 3 (H=1, K=256, N=64) ----------------
    conv_split_be<<<cdiv(Mp * 64, TB), TB>>>(hB, b2, Ahp, Alp, N, Mp);
    conv_wT<<<cdiv(64 * 256, TB), TB>>>(W3, Bhp, Blp, 256, 64, 256);
    gemm_mma<64><<<dim3(MT, 1), 256, SM64>>>(Ahp, Alp, Bhp, Blp, h3, N, 64, 256);
    node_logits<1><<<cdiv(N * 32, TB), TB>>>(h3, a3s, a3d, es, ed, den, N);
    zerok<<<cdiv(N * 16, TB), TB>>>((float4*)acc3, N * 16);
    edge_scores<1><<<cdiv(E2, TB), TB>>>(src, dst, E, E2, es, ed, ew, den);
    aggregate<1><<<cdiv(E2 * 32, TB), TB>>>(src, dst, E, E2, h3, ew, den, acc3);
    final_cls<<<cdiv(N * 32, TB), TB>>>(acc3, b3, Wc, bc, out, N);
}